// round 10
// baseline (speedup 1.0000x reference)
#include <cuda_runtime.h>
#include <math.h>
#include <stdint.h>

// Problem constants
#define BATCH 4
#define TLEN  1024
#define EDIM  1024
#define HEADS 16
#define SDIM  64
#define P2    2047   // 2*t - 1

// ---------------------------------------------------------------------------
// Scratch (device globals — no runtime allocation allowed)
// ---------------------------------------------------------------------------
__device__ float g_Q  [(size_t)BATCH * TLEN * EDIM];
__device__ float g_K  [(size_t)BATCH * TLEN * EDIM];
__device__ float g_V  [(size_t)BATCH * TLEN * EDIM];
__device__ float g_KP [(size_t)P2 * EDIM];
__device__ float g_dpt[(size_t)BATCH * HEADS * TLEN];
__device__ float g_cpp[(size_t)HEADS * P2];
__device__ float g_ATT[(size_t)BATCH * TLEN * EDIM];
__device__ float g_Wt [(size_t)5 * EDIM * EDIM];   // transposed weights [N,K]

// ---------------------------------------------------------------------------
// tf32 helpers. Mask split: hi = x with low 13 bits zeroed (tf32-exact),
// lo = x - hi exact in fp32 (Sterbenz).
// ---------------------------------------------------------------------------
__device__ __forceinline__ void msplit(float x, uint32_t& hi, uint32_t& lo) {
    uint32_t h = __float_as_uint(x) & 0xFFFFE000u;
    hi = h;
    lo = __float_as_uint(x - __uint_as_float(h));
}
__device__ __forceinline__ void mma_tf32(float* c,
    uint32_t a0, uint32_t a1, uint32_t a2, uint32_t a3,
    uint32_t b0, uint32_t b1)
{
    asm volatile(
        "mma.sync.aligned.m16n8k8.row.col.f32.tf32.tf32.f32 "
        "{%0,%1,%2,%3}, {%4,%5,%6,%7}, {%8,%9}, {%0,%1,%2,%3};"
        : "+f"(c[0]), "+f"(c[1]), "+f"(c[2]), "+f"(c[3])
        : "r"(a0), "r"(a1), "r"(a2), "r"(a3), "r"(b0), "r"(b1));
}
// x3 compensated: al*bh + ah*bl + ah*bh (residual ~2^-22)
__device__ __forceinline__ void mma_x3(float* c,
    const uint32_t* ah, const uint32_t* al,
    uint32_t bh0, uint32_t bh1, uint32_t bl0, uint32_t bl1)
{
    mma_tf32(c, al[0], al[1], al[2], al[3], bh0, bh1);
    mma_tf32(c, ah[0], ah[1], ah[2], ah[3], bl0, bl1);
    mma_tf32(c, ah[0], ah[1], ah[2], ah[3], bh0, bh1);
}

// cp.async helpers (baseline PTX, sm_80+); v=false -> zero-fill 16B
__device__ __forceinline__ void cpa16(void* smem_dst, const void* gsrc, bool v) {
    uint32_t s = (uint32_t)__cvta_generic_to_shared(smem_dst);
    int sz = v ? 16 : 0;
    asm volatile("cp.async.cg.shared.global [%0], [%1], 16, %2;"
                 :: "r"(s), "l"(gsrc), "r"(sz) : "memory");
}
#define CP_COMMIT() asm volatile("cp.async.commit_group;" ::: "memory")
#define CP_WAIT1()  asm volatile("cp.async.wait_group 1;" ::: "memory")
#define CP_WAIT0()  asm volatile("cp.async.wait_group 0;" ::: "memory")

// ---------------------------------------------------------------------------
// Batched weight transpose: dst[z][N,K] = src_z[K,N], 1024x1024 x5
// ---------------------------------------------------------------------------
__global__ void __launch_bounds__(256) transpose5_kernel(
    const float* __restrict__ W0, const float* __restrict__ W1,
    const float* __restrict__ W2, const float* __restrict__ W3,
    const float* __restrict__ W4, float* __restrict__ dstBase)
{
    __shared__ float t[32][33];
    int z = blockIdx.z;
    const float* src = (z == 0) ? W0 : (z == 1) ? W1 : (z == 2) ? W2
                     : (z == 3) ? W3 : W4;
    float* dst = dstBase + (size_t)z * EDIM * EDIM;
    int bx = blockIdx.x * 32, by = blockIdx.y * 32;
    int x = threadIdx.x, y = threadIdx.y;   // block (32, 8)
    #pragma unroll
    for (int i = 0; i < 32; i += 8)
        t[y + i][x] = src[(size_t)(by + y + i) * EDIM + bx + x];
    __syncthreads();
    #pragma unroll
    for (int i = 0; i < 32; i += 8)
        dst[(size_t)(bx + y + i) * EDIM + by + x] = t[x][y + i];
}

// ---------------------------------------------------------------------------
// Tensor-core GEMM tile body (tf32x3): C[bm:+128, bn:+128] = A @ Bt^T (+bias)
// BK=32, 256 threads (8 warps: 64m x 32n each), m16n8k8 x3 compensation.
// cp.async double-buffered staging (one k-tile prefetch depth).
// ---------------------------------------------------------------------------
#define PADK 36
#define GTILE (128 * PADK)                    // floats per matrix buffer
#define GEMM_SMEM_BYTES (4 * GTILE * 4)       // 2 bufs x (A + B) = 73728 B

__device__ __forceinline__ void gemm_stage(
    float* As, float* Bs,
    const float* __restrict__ A, const float* __restrict__ Bt,
    int M, int bm, int bn, int koff, int tid)
{
    #pragma unroll
    for (int r = 0; r < 4; r++) {
        int slot = tid + 256 * r;
        int row = slot >> 3, kc = (slot & 7) * 4;
        int grow = bm + row;
        bool v = grow < M;
        const float* ga = &A[(size_t)(v ? grow : 0) * EDIM + koff + kc];
        cpa16(&As[row * PADK + kc], ga, v);
        cpa16(&Bs[row * PADK + kc],
              &Bt[(size_t)(bn + row) * EDIM + koff + kc], true);
    }
    CP_COMMIT();
}

__device__ __forceinline__ void gemm_tile(
    const float* __restrict__ A, const float* __restrict__ Bt,
    const float* __restrict__ bias, float* __restrict__ C,
    int M, int hasBias, int bm, int bn)
{
    extern __shared__ float gsm[];
    float* Ab[2] = { gsm,             gsm + GTILE };
    float* Bb[2] = { gsm + 2 * GTILE, gsm + 3 * GTILE };

    const int tid  = threadIdx.x;
    const int wid  = tid >> 5;
    const int lane = tid & 31;
    const int wm = wid & 1;          // 0..1 : 64-row slice
    const int wn = wid >> 1;         // 0..3 : 32-col slice
    const int g = lane >> 2;         // group id 0..7
    const int t = lane & 3;          // thread-in-group 0..3

    gemm_stage(Ab[0], Bb[0], A, Bt, M, bm, bn, 0,  tid);
    gemm_stage(Ab[1], Bb[1], A, Bt, M, bm, bn, 32, tid);

    float acc[4][4][4];
    #pragma unroll
    for (int mi = 0; mi < 4; mi++)
        #pragma unroll
        for (int ni = 0; ni < 4; ni++)
            #pragma unroll
            for (int q = 0; q < 4; q++) acc[mi][ni][q] = 0.f;

    #pragma unroll 1
    for (int kt = 0; kt < 32; kt++) {
        if (kt + 1 < 32) CP_WAIT1(); else CP_WAIT0();
        __syncthreads();
        const float* As = Ab[kt & 1];
        const float* Bs = Bb[kt & 1];

        #pragma unroll
        for (int kk = 0; kk < 32; kk += 8) {
            uint32_t ah[4][4], al[4][4], bh[4][2], bl[4][2];
            #pragma unroll
            for (int mi = 0; mi < 4; mi++) {
                int r0 = wm * 64 + mi * 16 + g;
                int c0 = kk + t;
                msplit(As[r0 * PADK + c0],           ah[mi][0], al[mi][0]);
                msplit(As[(r0 + 8) * PADK + c0],     ah[mi][1], al[mi][1]);
                msplit(As[r0 * PADK + c0 + 4],       ah[mi][2], al[mi][2]);
                msplit(As[(r0 + 8) * PADK + c0 + 4], ah[mi][3], al[mi][3]);
            }
            #pragma unroll
            for (int ni = 0; ni < 4; ni++) {
                int rn = wn * 32 + ni * 8 + g;
                msplit(Bs[rn * PADK + kk + t],     bh[ni][0], bl[ni][0]);
                msplit(Bs[rn * PADK + kk + t + 4], bh[ni][1], bl[ni][1]);
            }
            #pragma unroll
            for (int mi = 0; mi < 4; mi++)
                #pragma unroll
                for (int ni = 0; ni < 4; ni++)
                    mma_x3(acc[mi][ni], ah[mi], al[mi],
                           bh[ni][0], bh[ni][1], bl[ni][0], bl[ni][1]);
        }
        __syncthreads();
        if (kt + 2 < 32)
            gemm_stage(Ab[kt & 1], Bb[kt & 1], A, Bt, M, bm, bn,
                       (kt + 2) * 32, tid);
    }

    #pragma unroll
    for (int mi = 0; mi < 4; mi++) {
        int row0 = bm + wm * 64 + mi * 16 + g;
        #pragma unroll
        for (int ni = 0; ni < 4; ni++) {
            int col = bn + wn * 32 + ni * 8 + t * 2;
            float b0 = hasBias ? bias[col] : 0.f;
            float b1 = hasBias ? bias[col + 1] : 0.f;
            if (row0 < M) {
                C[(size_t)row0 * EDIM + col]     = acc[mi][ni][0] + b0;
                C[(size_t)row0 * EDIM + col + 1] = acc[mi][ni][1] + b1;
            }
            if (row0 + 8 < M) {
                C[(size_t)(row0 + 8) * EDIM + col]     = acc[mi][ni][2] + b0;
                C[(size_t)(row0 + 8) * EDIM + col + 1] = acc[mi][ni][3] + b1;
            }
        }
    }
}

// Fused projections: z=0..2 -> Q/K/V from x; z=3 -> KP from pos_emb.
__global__ void __launch_bounds__(256, 2) fused_gemm_kernel(
    const float* __restrict__ x, const float* __restrict__ pos,
    const float* __restrict__ Wt0,
    float* __restrict__ Qb, float* __restrict__ Kb,
    float* __restrict__ Vb, float* __restrict__ KPb)
{
    const int z = blockIdx.z;
    const float* A = (z < 3) ? x : pos;
    const int M = (z < 3) ? (BATCH * TLEN) : P2;
    const int bm = blockIdx.y * 128;
    if (bm >= M) return;
    const float* Bt = Wt0 + (size_t)z * EDIM * EDIM;
    float* C = (z == 0) ? Qb : (z == 1) ? Kb : (z == 2) ? Vb : KPb;
    gemm_tile(A, Bt, nullptr, C, M, 0, bm, blockIdx.x * 128);
}

__global__ void __launch_bounds__(256, 2) gemmU_kernel(
    const float* __restrict__ A, const float* __restrict__ Bt,
    const float* __restrict__ bias, float* __restrict__ C)
{
    gemm_tile(A, Bt, bias, C, BATCH * TLEN, 1, blockIdx.y * 128, blockIdx.x * 128);
}

// ---------------------------------------------------------------------------
// Fused dpt + cpp
// ---------------------------------------------------------------------------
__global__ void __launch_bounds__(256) dptcpp_kernel(
    const float* __restrict__ Kt, const float* __restrict__ KP,
    const float* __restrict__ parma, const float* __restrict__ parmb,
    float* __restrict__ dpt, float* __restrict__ cpp)
{
    int idx = blockIdx.x * 256 + threadIdx.x;
    if (idx < BATCH * HEADS * TLEN) {
        int j = idx & (TLEN - 1);
        int h = (idx >> 10) & (HEADS - 1);
        int b = idx >> 14;
        const float* kr = Kt + ((size_t)(b * TLEN + j)) * EDIM + h * SDIM;
        const float* pa = parma + h * SDIM;
        float s = 0.f;
        #pragma unroll
        for (int ss = 0; ss < SDIM; ss++) s = fmaf(pa[ss], kr[ss], s);
        dpt[idx] = s;
    } else {
        int i2 = idx - BATCH * HEADS * TLEN;
        if (i2 >= HEADS * P2) return;
        int h = i2 / P2;
        int p = i2 - h * P2;
        const float* kr = KP + (size_t)p * EDIM + h * SDIM;
        const float* pb = parmb + h * SDIM;
        float s = 0.f;
        #pragma unroll
        for (int ss = 0; ss < SDIM; ss++) s = fmaf(pb[ss], kr[ss], s);
        cpp[i2] = s;
    }
}

// ---------------------------------------------------------------------------
// Tensor-core attention. One CTA per (b,h,64-row i-tile), 256 threads.
// Band-masked scores: E-rectangle fragments outside the needed diagonal band
// (and causally-dead fragments on the diagonal tile) are skipped entirely.
// Staging via cp.async. Scores warps: 2m x 4n (32x48); PV warps: 4m x 2n.
// ---------------------------------------------------------------------------
#define AP 68    // padded stride (conflict-free fragment reads: 4g+t)
#define VP 72    // V natural stride: banks 8t+g for PV reads, conflict-free
#define SP 196   // S matrix stride (64 rows x 192 cols)

#define ATTN_SMEM_FLOATS (64*AP + 192*AP + 64*VP + 64*AP + 64 + 128 + 64 + 64)

__global__ void __launch_bounds__(256, 2) attn_kernel(
    const float* __restrict__ Q, const float* __restrict__ Kt,
    const float* __restrict__ V, const float* __restrict__ KP,
    const float* __restrict__ dpt, const float* __restrict__ cpp,
    float* __restrict__ O)
{
    extern __shared__ float sm[];
    float* Qs   = sm;                   // [64][AP]  Q rows (A frag source)
    float* Bs   = Qs + 64 * AP;         // [192][AP] rows 0..63 = K, 64..191 = KP band
    float* Ssm  = Bs;                   // [64][SP]  aliases Bs after scores mma
    float* Vs   = Bs + 192 * AP;        // [64][VP]  natural: Vs[j][s]
    float* Psm  = Vs + 64 * VP;         // [64][AP]
    float* dpts = Psm + 64 * AP;        // [64]
    float* cpps = dpts + 64;            // [128]
    float* scale_sm = cpps + 128;       // [64]
    float* lsum_sm  = scale_sm + 64;    // [64]

    const int tid  = threadIdx.x;
    const int lane = tid & 31;
    const int wid  = tid >> 5;
    const int g = lane >> 2;            // 0..7
    const int t = lane & 3;             // 0..3
    const int rm = (wid & 1) * 32;      // scores m-base (32-row slice)
    const int cn = (wid >> 1) * 48;     // scores n-base (48-col slice)
    const int sm0 = (wid & 3) * 16;     // PV m-slice
    const int pn0 = (wid >> 2) * 32;    // PV n-slice
    const int tx = tid & 15, ty = tid >> 4;

    const int b = blockIdx.z, h = blockIdx.y;
    const int it = (int)gridDim.x - 1 - (int)blockIdx.x;  // big tiles first
    const int I0 = it * 64;
    const size_t headOff = (size_t)h * SDIM;

    // Stage Q tile once (float4)
    for (int idx = tid; idx < 1024; idx += 256) {
        int r = idx >> 4, s4 = (idx & 15) << 2;
        *(float4*)&Qs[r * AP + s4] =
            *(const float4*)&Q[((size_t)(b * TLEN + I0 + r)) * EDIM + headOff + s4];
    }

    float m_r[4], l_r[4];
    #pragma unroll
    for (int i = 0; i < 4; i++) { m_r[i] = -INFINITY; l_r[i] = 0.f; }
    float o_acc[4][4];
    #pragma unroll
    for (int n = 0; n < 4; n++)
        #pragma unroll
        for (int q = 0; q < 4; q++) o_acc[n][q] = 0.f;

    for (int jt = 0; jt <= it; jt++) {
        const int J0 = jt * 64;
        const int pbase = I0 + J0;
        const int d = I0 - J0;          // causal offset (>= 0)

        __syncthreads();   // prev tile's PV / Ssm reads done

        // ---- Stage K, KP band, V via cp.async (16B each) ----
        for (int idx = tid; idx < 1024; idx += 256) {
            int c = idx >> 4, s4 = (idx & 15) << 2;
            cpa16(&Bs[c * AP + s4],
                  &Kt[((size_t)(b * TLEN + J0 + c)) * EDIM + headOff + s4], true);
        }
        for (int idx = tid; idx < 2048; idx += 256) {
            int pl = idx >> 4, s4 = (idx & 15) << 2;
            int p = pbase + pl;
            bool v = p < P2;
            cpa16(&Bs[(64 + pl) * AP + s4],
                  &KP[(size_t)(v ? p : 0) * EDIM + headOff + s4], v);
        }
        for (int idx = tid; idx < 1024; idx += 256) {
            int j = idx >> 4, s4 = (idx & 15) << 2;
            cpa16(&Vs[j * VP + s4],
                  &V[((size_t)(b * TLEN + J0 + j)) * EDIM + headOff + s4], true);
        }
        CP_COMMIT();
        if (tid < 64) dpts[tid] = dpt[((size_t)(b * HEADS + h)) * TLEN + J0 + tid];
        if (tid < 128) {
            int p = pbase + tid;
            cpps[tid] = (p < P2) ? cpp[(size_t)h * P2 + p] : 0.f;
        }
        CP_WAIT0();
        __syncthreads();

        // ---- Fragment need-masks (warp-uniform) ----
        bool need[2][6];
        #pragma unroll
        for (int mi = 0; mi < 2; mi++) {
            int m0 = rm + 16 * mi;
            int cmax = m0 + 15 + d; if (cmax > 63) cmax = 63;
            #pragma unroll
            for (int nt = 0; nt < 6; nt++) {
                int n0 = cn + nt * 8;
                if (n0 < 64) {
                    need[mi][nt] = (n0 <= m0 + 15 + d);
                } else {
                    int pl0 = n0 - 64;
                    need[mi][nt] = (pl0 + 7 >= m0) && (pl0 <= m0 + 15 + cmax);
                }
            }
        }

        // ---- Scores mma: S[64x192] = Q @ Bs^T (tf32x3, band-masked) ----
        float sacc[2][6][4];
        #pragma unroll
        for (int mi = 0; mi < 2; mi++)
            #pragma unroll
            for (int n = 0; n < 6; n++)
                #pragma unroll
                for (int q = 0; q < 4; q++) sacc[mi][n][q] = 0.f;

        #pragma unroll
        for (int kk = 0; kk < 64; kk += 8) {
            uint32_t ah[2][4], al[2][4];
            #pragma unroll
            for (int mi = 0; mi < 2; mi++) {
                int r0 = rm + 16 * mi + g;
                msplit(Qs[r0 * AP + kk + t],           ah[mi][0], al[mi][0]);
                msplit(Qs[(r0 + 8) * AP + kk + t],     ah[mi][1], al[mi][1]);
                msplit(Qs[r0 * AP + kk + t + 4],       ah[mi][2], al[mi][2]);
                msplit(Qs[(r0 + 8) * AP + kk + t + 4], ah[mi][3], al[mi][3]);
            }
            #pragma unroll
            for (int nt = 0; nt < 6; nt++) {
                if (!need[0][nt] && !need[1][nt]) continue;
                int n0 = cn + nt * 8;
                uint32_t bh0, bl0, bh1, bl1;
                msplit(Bs[(n0 + g) * AP + kk + t],     bh0, bl0);
                msplit(Bs[(n0 + g) * AP + kk + t + 4], bh1, bl1);
                if (need[0][nt])
                    mma_x3(sacc[0][nt], ah[0], al[0], bh0, bh1, bl0, bl1);
                if (need[1][nt])
                    mma_x3(sacc[1][nt], ah[1], al[1], bh0, bh1, bl0, bl1);
            }
        }

        __syncthreads();   // all warps done reading Bs; overwrite as Ssm
        #pragma unroll
        for (int mi = 0; mi < 2; mi++) {
            int r0 = rm + 16 * mi + g;
            #pragma unroll
            for (int nt = 0; nt < 6; nt++) {
                if (!need[mi][nt]) continue;
                int n0 = cn + nt * 8 + 2 * t;
                Ssm[r0 * SP + n0]           = sacc[mi][nt][0];
                Ssm[r0 * SP + n0 + 1]       = sacc[mi][nt][1];
                Ssm[(r0 + 8) * SP + n0]     = sacc[mi][nt][2];
                Ssm[(r0 + 8) * SP + n0 + 1] = sacc[mi][nt][3];
            }
        }
        __syncthreads();

        // ---- Softmax (fp32 SIMT): rows ty+16i, cols tx+16j ----
        #pragma unroll
        for (int i = 0; i < 4; i++) {
            int r = ty + 16 * i;
            float sc[4];
            float mx = -INFINITY;
            #pragma unroll
            for (int j = 0; j < 4; j++) {
                int c = tx + 16 * j;
                float v = Ssm[r * SP + c] + Ssm[r * SP + 64 + r + c]
                        + dpts[c] + cpps[r + c];
                if (c > r + d) v = -1e30f;
                sc[j] = v;
                mx = fmaxf(mx, v);
            }
            #pragma unroll
            for (int off = 8; off >= 1; off >>= 1)
                mx = fmaxf(mx, __shfl_xor_sync(0xffffffffu, mx, off));
            float mnew = fmaxf(m_r[i], mx);
            float scale = __expf(m_r[i] - mnew);
            m_r[i] = mnew;
            float rs = 0.f;
            #pragma unroll
            for (int j = 0; j < 4; j++) {
                float p = __expf(sc[j] - mnew);
                Psm[r * AP + tx + 16 * j] = p;
                rs += p;
            }
            #pragma unroll
            for (int off = 8; off >= 1; off >>= 1)
                rs += __shfl_xor_sync(0xffffffffu, rs, off);
            l_r[i] = l_r[i] * scale + rs;
            if (tx == 0) {
                scale_sm[r] = scale;
                lsum_sm[r]  = l_r[i];
            }
        }
        __syncthreads();

        // ---- PV mma: O = O*scale + P @ V (tf32x3, 16x32 per warp) ----
        const float sA = scale_sm[sm0 + g];
        const float sB = scale_sm[sm0 + g + 8];
        #pragma unroll
        for (int nt = 0; nt < 4; nt++) {
            o_acc[nt][0] *= sA; o_acc[nt][1] *= sA;
            o_acc[nt][2] *= sB; o_acc[nt][3] *= sB;
        }
        #pragma unroll
        for (int kk = 0; kk < 64; kk += 8) {
            uint32_t ah[4], al[4];
            msplit(Psm[(sm0 + g) * AP + kk + t],         ah[0], al[0]);
            msplit(Psm[(sm0 + g + 8) * AP + kk + t],     ah[1], al[1]);
            msplit(Psm[(sm0 + g) * AP + kk + t + 4],     ah[2], al[2]);
            msplit(Psm[(sm0 + g + 8) * AP + kk + t + 4], ah[3], al[3]);
            #pragma unroll
            for (int nt = 0; nt < 4; nt++) {
                int n0 = pn0 + nt * 8;
                uint32_t bh0, bl0, bh1, bl1;
                msplit(Vs[(kk + t) * VP + n0 + g],     bh0, bl0);
                msplit(Vs[(kk + t + 4) * VP + n0 + g], bh1, bl1);
                mma_x3(o_acc[nt], ah, al, bh0, bh1, bl0, bl1);
            }
        }
    }

    __syncthreads();
    const float invA = 1.f / lsum_sm[sm0 + g];
    const float invB = 1.f / lsum_sm[sm0 + g + 8];
    const size_t row0 = (size_t)(b * TLEN + I0 + sm0 + g) * EDIM;
    const size_t row1 = row0 + 8 * EDIM;
    #pragma unroll
    for (int nt = 0; nt < 4; nt++) {
        size_t col = headOff + pn0 + nt * 8 + 2 * t;
        O[row0 + col]     = o_acc[nt][0] * invA;
        O[row0 + col + 1] = o_acc[nt][1] * invA;
        O[row1 + col]     = o_acc[nt][2] * invB;
        O[row1 + col + 1] = o_acc[nt][3] * invB;
    }
}

// ---------------------------------------------------------------------------
// Launch (5 launches total)
// ---------------------------------------------------------------------------
extern "C" void kernel_launch(void* const* d_in, const int* in_sizes, int n_in,
                              void* d_out, int out_size)
{
    const float* x     = (const float*)d_in[0];
    const float* Wq    = (const float*)d_in[1];
    const float* Wk    = (const float*)d_in[2];
    const float* Wkp   = (const float*)d_in[3];
    const float* Wv    = (const float*)d_in[4];
    const float* Wu    = (const float*)d_in[5];
    const float* bu    = (const float*)d_in[6];
    const float* parma = (const float*)d_in[7];
    const float* parmb = (const float*)d_in[8];
    const float* pos   = (const float*)d_in[9];
    float* out = (float*)d_out;

    float *Qb, *Kb, *Vb, *KPb, *dptb, *cppb, *ATTb, *Wtb;
    cudaGetSymbolAddress((void**)&Qb,   g_Q);
    cudaGetSymbolAddress((void**)&Kb,   g_K);
    cudaGetSymbolAddress((void**)&Vb,   g_V);
    cudaGetSymbolAddress((void**)&KPb,  g_KP);
    cudaGetSymbolAddress((void**)&dptb, g_dpt);
    cudaGetSymbolAddress((void**)&cppb, g_cpp);
    cudaGetSymbolAddress((void**)&ATTb, g_ATT);
    cudaGetSymbolAddress((void**)&Wtb,  g_Wt);

    const size_t WSZ = (size_t)EDIM * EDIM;

    // 1) transpose all 5 weights (g_Wt order: Wq, Wk, Wv, Wkp, Wu)
    transpose5_kernel<<<dim3(32, 32, 5), dim3(32, 8)>>>(Wq, Wk, Wv, Wkp, Wu, Wtb);

    // 2) fused Q/K/V/KP projections (cp.async double-buffered GEMM)
    cudaFuncSetAttribute(fused_gemm_kernel,
                         cudaFuncAttributeMaxDynamicSharedMemorySize,
                         GEMM_SMEM_BYTES);
    fused_gemm_kernel<<<dim3(8, 32, 4), 256, GEMM_SMEM_BYTES>>>(
        x, pos, Wtb, Qb, Kb, Vb, KPb);

    // 3) fused dpt + cpp
    const int total_small = BATCH * HEADS * TLEN + HEADS * P2;
    dptcpp_kernel<<<(total_small + 255) / 256, 256>>>(Kb, KPb, parma, parmb,
                                                      dptb, cppb);

    // 4) attention
    size_t smemBytes = (size_t)ATTN_SMEM_FLOATS * sizeof(float);
    cudaFuncSetAttribute(attn_kernel,
                         cudaFuncAttributeMaxDynamicSharedMemorySize,
                         (int)smemBytes);
    attn_kernel<<<dim3(TLEN / 64, HEADS, BATCH), 256, smemBytes>>>(
        Qb, Kb, Vb, KPb, dptb, cppb, ATTb);

    // 5) output projection (+bias)
    cudaFuncSetAttribute(gemmU_kernel,
                         cudaFuncAttributeMaxDynamicSharedMemorySize,
                         GEMM_SMEM_BYTES);
    gemmU_kernel<<<dim3(8, 32), 256, GEMM_SMEM_BYTES>>>(
        ATTb, Wtb + 4 * WSZ, bu, out);
}

// round 11
// speedup vs baseline: 1.2140x; 1.2140x over previous
#include <cuda_runtime.h>
#include <cuda_bf16.h>
#include <math.h>
#include <stdint.h>

// Problem constants
#define BATCH 4
#define TLEN  1024
#define EDIM  1024
#define HEADS 16
#define SDIM  64
#define P2    2047   // 2*t - 1

// ---------------------------------------------------------------------------
// Scratch (device globals — no runtime allocation allowed)
// ---------------------------------------------------------------------------
__device__ float g_Q  [(size_t)BATCH * TLEN * EDIM];
__device__ float g_K  [(size_t)BATCH * TLEN * EDIM];
__device__ float g_V  [(size_t)BATCH * TLEN * EDIM];
__device__ float g_KP [(size_t)P2 * EDIM];
__device__ float g_dpt[(size_t)BATCH * HEADS * TLEN];
__device__ float g_cpp[(size_t)HEADS * P2];
// bf16 hi/lo planes
__device__ __nv_bfloat16 g_Xh [(size_t)BATCH * TLEN * EDIM];
__device__ __nv_bfloat16 g_Xl [(size_t)BATCH * TLEN * EDIM];
__device__ __nv_bfloat16 g_Ph [(size_t)P2 * EDIM];
__device__ __nv_bfloat16 g_Pl [(size_t)P2 * EDIM];
__device__ __nv_bfloat16 g_Wh [(size_t)5 * EDIM * EDIM];  // transposed [N,K]
__device__ __nv_bfloat16 g_Wl [(size_t)5 * EDIM * EDIM];
__device__ __nv_bfloat16 g_ATTh[(size_t)BATCH * TLEN * EDIM];
__device__ __nv_bfloat16 g_ATTl[(size_t)BATCH * TLEN * EDIM];

// ---------------------------------------------------------------------------
// helpers
// ---------------------------------------------------------------------------
__device__ __forceinline__ void msplit(float x, uint32_t& hi, uint32_t& lo) {
    uint32_t h = __float_as_uint(x) & 0xFFFFE000u;   // tf32 mask split
    hi = h;
    lo = __float_as_uint(x - __uint_as_float(h));
}
__device__ __forceinline__ void mma_tf32(float* c,
    uint32_t a0, uint32_t a1, uint32_t a2, uint32_t a3,
    uint32_t b0, uint32_t b1)
{
    asm volatile(
        "mma.sync.aligned.m16n8k8.row.col.f32.tf32.tf32.f32 "
        "{%0,%1,%2,%3}, {%4,%5,%6,%7}, {%8,%9}, {%0,%1,%2,%3};"
        : "+f"(c[0]), "+f"(c[1]), "+f"(c[2]), "+f"(c[3])
        : "r"(a0), "r"(a1), "r"(a2), "r"(a3), "r"(b0), "r"(b1));
}
__device__ __forceinline__ void mma_x3(float* c,
    const uint32_t* ah, const uint32_t* al,
    uint32_t bh0, uint32_t bh1, uint32_t bl0, uint32_t bl1)
{
    mma_tf32(c, al[0], al[1], al[2], al[3], bh0, bh1);
    mma_tf32(c, ah[0], ah[1], ah[2], ah[3], bl0, bl1);
    mma_tf32(c, ah[0], ah[1], ah[2], ah[3], bh0, bh1);
}
__device__ __forceinline__ void mma_bf16(float* c,
    uint32_t a0, uint32_t a1, uint32_t a2, uint32_t a3,
    uint32_t b0, uint32_t b1)
{
    asm volatile(
        "mma.sync.aligned.m16n8k16.row.col.f32.bf16.bf16.f32 "
        "{%0,%1,%2,%3}, {%4,%5,%6,%7}, {%8,%9}, {%0,%1,%2,%3};"
        : "+f"(c[0]), "+f"(c[1]), "+f"(c[2]), "+f"(c[3])
        : "r"(a0), "r"(a1), "r"(a2), "r"(a3), "r"(b0), "r"(b1));
}
__device__ __forceinline__ void mma_bf16_x3(float* c,
    const uint32_t* ah, const uint32_t* al,
    uint32_t bh0, uint32_t bh1, uint32_t bl0, uint32_t bl1)
{
    mma_bf16(c, al[0], al[1], al[2], al[3], bh0, bh1);
    mma_bf16(c, ah[0], ah[1], ah[2], ah[3], bl0, bl1);
    mma_bf16(c, ah[0], ah[1], ah[2], ah[3], bh0, bh1);
}
// pack two fp32 into (hi bf16x2, lo bf16x2)
__device__ __forceinline__ void bsplit2(float v0, float v1,
                                        uint32_t& hi, uint32_t& lo)
{
    __nv_bfloat162 h = __float22bfloat162_rn(make_float2(v0, v1));
    float r0 = v0 - __bfloat162float(h.x);
    float r1 = v1 - __bfloat162float(h.y);
    __nv_bfloat162 l = __float22bfloat162_rn(make_float2(r0, r1));
    hi = *(uint32_t*)&h;
    lo = *(uint32_t*)&l;
}

// cp.async helpers (baseline PTX, sm_80+); v=false -> zero-fill 16B
__device__ __forceinline__ void cpa16(void* smem_dst, const void* gsrc, bool v) {
    uint32_t s = (uint32_t)__cvta_generic_to_shared(smem_dst);
    int sz = v ? 16 : 0;
    asm volatile("cp.async.cg.shared.global [%0], [%1], 16, %2;"
                 :: "r"(s), "l"(gsrc), "r"(sz) : "memory");
}
#define CP_COMMIT() asm volatile("cp.async.commit_group;" ::: "memory")
#define CP_WAIT1()  asm volatile("cp.async.wait_group 1;" ::: "memory")
#define CP_WAIT0()  asm volatile("cp.async.wait_group 0;" ::: "memory")

// ---------------------------------------------------------------------------
// Transpose 5 weights into bf16 hi/lo planes: dst[z][N][K] = split(src_z[K,N])
// ---------------------------------------------------------------------------
__global__ void __launch_bounds__(256) transpose5_kernel(
    const float* __restrict__ W0, const float* __restrict__ W1,
    const float* __restrict__ W2, const float* __restrict__ W3,
    const float* __restrict__ W4,
    __nv_bfloat16* __restrict__ dstHi, __nv_bfloat16* __restrict__ dstLo)
{
    __shared__ float t[32][33];
    int z = blockIdx.z;
    const float* src = (z == 0) ? W0 : (z == 1) ? W1 : (z == 2) ? W2
                     : (z == 3) ? W3 : W4;
    size_t base = (size_t)z * EDIM * EDIM;
    int bx = blockIdx.x * 32, by = blockIdx.y * 32;
    int x = threadIdx.x, y = threadIdx.y;   // block (32, 8)
    #pragma unroll
    for (int i = 0; i < 32; i += 8)
        t[y + i][x] = src[(size_t)(by + y + i) * EDIM + bx + x];
    __syncthreads();
    #pragma unroll
    for (int i = 0; i < 32; i += 8) {
        float v = t[x][y + i];
        __nv_bfloat16 hb = __float2bfloat16_rn(v);
        size_t o = base + (size_t)(bx + y + i) * EDIM + by + x;
        dstHi[o] = hb;
        dstLo[o] = __float2bfloat16_rn(v - __bfloat162float(hb));
    }
}

// ---------------------------------------------------------------------------
// Convert fp32 array to bf16 hi/lo planes (pairwise)
// ---------------------------------------------------------------------------
__global__ void __launch_bounds__(256) cvt_planes_kernel(
    const float2* __restrict__ src, uint32_t* __restrict__ hi,
    uint32_t* __restrict__ lo, int npairs)
{
    int i = blockIdx.x * 256 + threadIdx.x;
    if (i >= npairs) return;
    float2 v = src[i];
    uint32_t h, l;
    bsplit2(v.x, v.y, h, l);
    hi[i] = h;
    lo[i] = l;
}

// ---------------------------------------------------------------------------
// bf16x3 tensor-core GEMM: C[bm:+128, bn:+128] = A @ Bt^T (+bias)
// A, Bt given as hi/lo bf16 planes [rows][1024]. BK=32 (2 k16 steps),
// 256 threads (8 warps: 64m x 32n), cp.async double-buffered.
// ---------------------------------------------------------------------------
#define GPW 20                         // uint32 words per smem plane row
#define PLANE_W (128 * GPW)            // 2560 words per plane
#define GEMM_SMEM_BYTES (8 * PLANE_W * 4)   // 81920 B

__device__ __forceinline__ void gemm_stage_bf16(
    uint32_t* s,   // buffer base: [Ah][Al][Bh][Bl] planes
    const uint32_t* __restrict__ Ah, const uint32_t* __restrict__ Al,
    const uint32_t* __restrict__ Bh, const uint32_t* __restrict__ Bl,
    int M, int bm, int bn, int koffw, int tid)
{
    #pragma unroll
    for (int r = 0; r < 2; r++) {
        int slot = tid + 256 * r;          // 0..511
        int row = slot >> 2, ch = (slot & 3) * 4;   // word offset
        int grow = bm + row;
        bool v = grow < M;
        size_t ga = (size_t)(v ? grow : 0) * 512 + koffw + ch;
        size_t gb = (size_t)(bn + row) * 512 + koffw + ch;
        uint32_t* sd = s + row * GPW + ch;
        cpa16(sd,               &Ah[ga], v);
        cpa16(sd + PLANE_W,     &Al[ga], v);
        cpa16(sd + 2 * PLANE_W, &Bh[gb], true);
        cpa16(sd + 3 * PLANE_W, &Bl[gb], true);
    }
    CP_COMMIT();
}

__device__ __forceinline__ void gemm_tile(
    const uint32_t* __restrict__ Ah, const uint32_t* __restrict__ Al,
    const uint32_t* __restrict__ Bh, const uint32_t* __restrict__ Bl,
    const float* __restrict__ bias, float* __restrict__ C,
    int M, int hasBias, int bm, int bn)
{
    extern __shared__ uint32_t gsm[];
    uint32_t* buf0 = gsm;
    uint32_t* buf1 = gsm + 4 * PLANE_W;

    const int tid  = threadIdx.x;
    const int wid  = tid >> 5;
    const int lane = tid & 31;
    const int wm = wid & 1;          // 0..1 : 64-row slice
    const int wn = wid >> 1;         // 0..3 : 32-col slice
    const int g = lane >> 2;         // group id 0..7
    const int t = lane & 3;          // thread-in-group 0..3

    gemm_stage_bf16(buf0, Ah, Al, Bh, Bl, M, bm, bn, 0,  tid);
    gemm_stage_bf16(buf1, Ah, Al, Bh, Bl, M, bm, bn, 16, tid);

    float acc[4][4][4];
    #pragma unroll
    for (int mi = 0; mi < 4; mi++)
        #pragma unroll
        for (int ni = 0; ni < 4; ni++)
            #pragma unroll
            for (int q = 0; q < 4; q++) acc[mi][ni][q] = 0.f;

    #pragma unroll 1
    for (int kt = 0; kt < 32; kt++) {
        if (kt + 1 < 32) CP_WAIT1(); else CP_WAIT0();
        __syncthreads();
        const uint32_t* s = (kt & 1) ? buf1 : buf0;
        const uint32_t* Ahs = s;
        const uint32_t* Als = s + PLANE_W;
        const uint32_t* Bhs = s + 2 * PLANE_W;
        const uint32_t* Bls = s + 3 * PLANE_W;

        #pragma unroll
        for (int ks = 0; ks < 2; ks++) {
            const int kb = ks * 8;
            uint32_t ah[4][4], al[4][4];
            #pragma unroll
            for (int mi = 0; mi < 4; mi++) {
                int r0 = wm * 64 + mi * 16 + g;
                ah[mi][0] = Ahs[r0 * GPW + kb + t];
                ah[mi][1] = Ahs[(r0 + 8) * GPW + kb + t];
                ah[mi][2] = Ahs[r0 * GPW + kb + t + 4];
                ah[mi][3] = Ahs[(r0 + 8) * GPW + kb + t + 4];
                al[mi][0] = Als[r0 * GPW + kb + t];
                al[mi][1] = Als[(r0 + 8) * GPW + kb + t];
                al[mi][2] = Als[r0 * GPW + kb + t + 4];
                al[mi][3] = Als[(r0 + 8) * GPW + kb + t + 4];
            }
            #pragma unroll
            for (int ni = 0; ni < 4; ni++) {
                int rn = wn * 32 + ni * 8 + g;
                uint32_t bh0 = Bhs[rn * GPW + kb + t];
                uint32_t bh1 = Bhs[rn * GPW + kb + t + 4];
                uint32_t bl0 = Bls[rn * GPW + kb + t];
                uint32_t bl1 = Bls[rn * GPW + kb + t + 4];
                #pragma unroll
                for (int mi = 0; mi < 4; mi++)
                    mma_bf16_x3(acc[mi][ni], ah[mi], al[mi], bh0, bh1, bl0, bl1);
            }
        }
        __syncthreads();
        if (kt + 2 < 32)
            gemm_stage_bf16((kt & 1) ? buf1 : buf0, Ah, Al, Bh, Bl,
                            M, bm, bn, (kt + 2) * 16, tid);
    }

    #pragma unroll
    for (int mi = 0; mi < 4; mi++) {
        int row0 = bm + wm * 64 + mi * 16 + g;
        #pragma unroll
        for (int ni = 0; ni < 4; ni++) {
            int col = bn + wn * 32 + ni * 8 + t * 2;
            float b0 = hasBias ? bias[col] : 0.f;
            float b1 = hasBias ? bias[col + 1] : 0.f;
            if (row0 < M) {
                C[(size_t)row0 * EDIM + col]     = acc[mi][ni][0] + b0;
                C[(size_t)row0 * EDIM + col + 1] = acc[mi][ni][1] + b1;
            }
            if (row0 + 8 < M) {
                C[(size_t)(row0 + 8) * EDIM + col]     = acc[mi][ni][2] + b0;
                C[(size_t)(row0 + 8) * EDIM + col + 1] = acc[mi][ni][3] + b1;
            }
        }
    }
}

// Fused projections: z=0..2 -> Q/K/V from x planes; z=3 -> KP from pos planes.
__global__ void __launch_bounds__(256, 2) fused_gemm_kernel(
    const uint32_t* __restrict__ Xh, const uint32_t* __restrict__ Xl,
    const uint32_t* __restrict__ Ph, const uint32_t* __restrict__ Pl,
    const uint32_t* __restrict__ Wh, const uint32_t* __restrict__ Wl,
    float* __restrict__ Qb, float* __restrict__ Kb,
    float* __restrict__ Vb, float* __restrict__ KPb)
{
    const int z = blockIdx.z;
    const uint32_t* Ah = (z < 3) ? Xh : Ph;
    const uint32_t* Al = (z < 3) ? Xl : Pl;
    const int M = (z < 3) ? (BATCH * TLEN) : P2;
    const int bm = blockIdx.y * 128;
    if (bm >= M) return;
    const uint32_t* Bh = Wh + (size_t)z * EDIM * EDIM / 2;
    const uint32_t* Bl = Wl + (size_t)z * EDIM * EDIM / 2;
    float* C = (z == 0) ? Qb : (z == 1) ? Kb : (z == 2) ? Vb : KPb;
    gemm_tile(Ah, Al, Bh, Bl, nullptr, C, M, 0, bm, blockIdx.x * 128);
}

__global__ void __launch_bounds__(256, 2) gemmU_kernel(
    const uint32_t* __restrict__ Ah, const uint32_t* __restrict__ Al,
    const uint32_t* __restrict__ Bh, const uint32_t* __restrict__ Bl,
    const float* __restrict__ bias, float* __restrict__ C)
{
    gemm_tile(Ah, Al, Bh, Bl, bias, C, BATCH * TLEN, 1,
              blockIdx.y * 128, blockIdx.x * 128);
}

// ---------------------------------------------------------------------------
// Fused dpt + cpp
// ---------------------------------------------------------------------------
__global__ void __launch_bounds__(256) dptcpp_kernel(
    const float* __restrict__ Kt, const float* __restrict__ KP,
    const float* __restrict__ parma, const float* __restrict__ parmb,
    float* __restrict__ dpt, float* __restrict__ cpp)
{
    int idx = blockIdx.x * 256 + threadIdx.x;
    if (idx < BATCH * HEADS * TLEN) {
        int j = idx & (TLEN - 1);
        int h = (idx >> 10) & (HEADS - 1);
        int b = idx >> 14;
        const float* kr = Kt + ((size_t)(b * TLEN + j)) * EDIM + h * SDIM;
        const float* pa = parma + h * SDIM;
        float s = 0.f;
        #pragma unroll
        for (int ss = 0; ss < SDIM; ss++) s = fmaf(pa[ss], kr[ss], s);
        dpt[idx] = s;
    } else {
        int i2 = idx - BATCH * HEADS * TLEN;
        if (i2 >= HEADS * P2) return;
        int h = i2 / P2;
        int p = i2 - h * P2;
        const float* kr = KP + (size_t)p * EDIM + h * SDIM;
        const float* pb = parmb + h * SDIM;
        float s = 0.f;
        #pragma unroll
        for (int ss = 0; ss < SDIM; ss++) s = fmaf(pb[ss], kr[ss], s);
        cpp[i2] = s;
    }
}

// ---------------------------------------------------------------------------
// Tensor-core attention (round-10 proven version; epilogue writes ATT as
// bf16 hi/lo planes for the bf16 gemmU). tf32x3 + band-masked scores.
// ---------------------------------------------------------------------------
#define AP 68    // padded stride (conflict-free fragment reads: 4g+t)
#define VP 72    // V natural stride: banks 8t+g for PV reads, conflict-free
#define SP 196   // S matrix stride (64 rows x 192 cols)

#define ATTN_SMEM_FLOATS (64*AP + 192*AP + 64*VP + 64*AP + 64 + 128 + 64 + 64)

__global__ void __launch_bounds__(256, 2) attn_kernel(
    const float* __restrict__ Q, const float* __restrict__ Kt,
    const float* __restrict__ V, const float* __restrict__ KP,
    const float* __restrict__ dpt, const float* __restrict__ cpp,
    uint32_t* __restrict__ Oh, uint32_t* __restrict__ Ol)
{
    extern __shared__ float sm[];
    float* Qs   = sm;                   // [64][AP]
    float* Bs   = Qs + 64 * AP;         // [192][AP] K rows 0..63, KP band 64..191
    float* Ssm  = Bs;                   // [64][SP] aliases Bs after scores mma
    float* Vs   = Bs + 192 * AP;        // [64][VP] natural: Vs[j][s]
    float* Psm  = Vs + 64 * VP;         // [64][AP]
    float* dpts = Psm + 64 * AP;        // [64]
    float* cpps = dpts + 64;            // [128]
    float* scale_sm = cpps + 128;       // [64]
    float* lsum_sm  = scale_sm + 64;    // [64]

    const int tid  = threadIdx.x;
    const int lane = tid & 31;
    const int wid  = tid >> 5;
    const int g = lane >> 2;
    const int t = lane & 3;
    const int rm = (wid & 1) * 32;      // scores m-base
    const int cn = (wid >> 1) * 48;     // scores n-base
    const int sm0 = (wid & 3) * 16;     // PV m-slice
    const int pn0 = (wid >> 2) * 32;    // PV n-slice
    const int tx = tid & 15, ty = tid >> 4;

    const int b = blockIdx.z, h = blockIdx.y;
    const int it = (int)gridDim.x - 1 - (int)blockIdx.x;
    const int I0 = it * 64;
    const size_t headOff = (size_t)h * SDIM;

    for (int idx = tid; idx < 1024; idx += 256) {
        int r = idx >> 4, s4 = (idx & 15) << 2;
        *(float4*)&Qs[r * AP + s4] =
            *(const float4*)&Q[((size_t)(b * TLEN + I0 + r)) * EDIM + headOff + s4];
    }

    float m_r[4], l_r[4];
    #pragma unroll
    for (int i = 0; i < 4; i++) { m_r[i] = -INFINITY; l_r[i] = 0.f; }
    float o_acc[4][4];
    #pragma unroll
    for (int n = 0; n < 4; n++)
        #pragma unroll
        for (int q = 0; q < 4; q++) o_acc[n][q] = 0.f;

    for (int jt = 0; jt <= it; jt++) {
        const int J0 = jt * 64;
        const int pbase = I0 + J0;
        const int d = I0 - J0;

        __syncthreads();

        for (int idx = tid; idx < 1024; idx += 256) {
            int c = idx >> 4, s4 = (idx & 15) << 2;
            cpa16(&Bs[c * AP + s4],
                  &Kt[((size_t)(b * TLEN + J0 + c)) * EDIM + headOff + s4], true);
        }
        for (int idx = tid; idx < 2048; idx += 256) {
            int pl = idx >> 4, s4 = (idx & 15) << 2;
            int p = pbase + pl;
            bool v = p < P2;
            cpa16(&Bs[(64 + pl) * AP + s4],
                  &KP[(size_t)(v ? p : 0) * EDIM + headOff + s4], v);
        }
        for (int idx = tid; idx < 1024; idx += 256) {
            int j = idx >> 4, s4 = (idx & 15) << 2;
            cpa16(&Vs[j * VP + s4],
                  &V[((size_t)(b * TLEN + J0 + j)) * EDIM + headOff + s4], true);
        }
        CP_COMMIT();
        if (tid < 64) dpts[tid] = dpt[((size_t)(b * HEADS + h)) * TLEN + J0 + tid];
        if (tid < 128) {
            int p = pbase + tid;
            cpps[tid] = (p < P2) ? cpp[(size_t)h * P2 + p] : 0.f;
        }
        CP_WAIT0();
        __syncthreads();

        bool need[2][6];
        #pragma unroll
        for (int mi = 0; mi < 2; mi++) {
            int m0 = rm + 16 * mi;
            int cmax = m0 + 15 + d; if (cmax > 63) cmax = 63;
            #pragma unroll
            for (int nt = 0; nt < 6; nt++) {
                int n0 = cn + nt * 8;
                if (n0 < 64) {
                    need[mi][nt] = (n0 <= m0 + 15 + d);
                } else {
                    int pl0 = n0 - 64;
                    need[mi][nt] = (pl0 + 7 >= m0) && (pl0 <= m0 + 15 + cmax);
                }
            }
        }

        float sacc[2][6][4];
        #pragma unroll
        for (int mi = 0; mi < 2; mi++)
            #pragma unroll
            for (int n = 0; n < 6; n++)
                #pragma unroll
                for (int q = 0; q < 4; q++) sacc[mi][n][q] = 0.f;

        #pragma unroll
        for (int kk = 0; kk < 64; kk += 8) {
            uint32_t ah[2][4], al[2][4];
            #pragma unroll
            for (int mi = 0; mi < 2; mi++) {
                int r0 = rm + 16 * mi + g;
                msplit(Qs[r0 * AP + kk + t],           ah[mi][0], al[mi][0]);
                msplit(Qs[(r0 + 8) * AP + kk + t],     ah[mi][1], al[mi][1]);
                msplit(Qs[r0 * AP + kk + t + 4],       ah[mi][2], al[mi][2]);
                msplit(Qs[(r0 + 8) * AP + kk + t + 4], ah[mi][3], al[mi][3]);
            }
            #pragma unroll
            for (int nt = 0; nt < 6; nt++) {
                if (!need[0][nt] && !need[1][nt]) continue;
                int n0 = cn + nt * 8;
                uint32_t bh0, bl0, bh1, bl1;
                msplit(Bs[(n0 + g) * AP + kk + t],     bh0, bl0);
                msplit(Bs[(n0 + g) * AP + kk + t + 4], bh1, bl1);
                if (need[0][nt])
                    mma_x3(sacc[0][nt], ah[0], al[0], bh0, bh1, bl0, bl1);
                if (need[1][nt])
                    mma_x3(sacc[1][nt], ah[1], al[1], bh0, bh1, bl0, bl1);
            }
        }

        __syncthreads();
        #pragma unroll
        for (int mi = 0; mi < 2; mi++) {
            int r0 = rm + 16 * mi + g;
            #pragma unroll
            for (int nt = 0; nt < 6; nt++) {
                if (!need[mi][nt]) continue;
                int n0 = cn + nt * 8 + 2 * t;
                Ssm[r0 * SP + n0]           = sacc[mi][nt][0];
                Ssm[r0 * SP + n0 + 1]       = sacc[mi][nt][1];
                Ssm[(r0 + 8) * SP + n0]     = sacc[mi][nt][2];
                Ssm[(r0 + 8) * SP + n0 + 1] = sacc[mi][nt][3];
            }
        }
        __syncthreads();

        #pragma unroll
        for (int i = 0; i < 4; i++) {
            int r = ty + 16 * i;
            float sc[4];
            float mx = -INFINITY;
            #pragma unroll
            for (int j = 0; j < 4; j++) {
                int c = tx + 16 * j;
                float v = Ssm[r * SP + c] + Ssm[r * SP + 64 + r + c]
                        + dpts[c] + cpps[r + c];
                if (c > r + d) v = -1e30f;
                sc[j] = v;
                mx = fmaxf(mx, v);
            }
            #pragma unroll
            for (int off = 8; off >= 1; off >>= 1)
                mx = fmaxf(mx, __shfl_xor_sync(0xffffffffu, mx, off));
            float mnew = fmaxf(m_r[i], mx);
            float scale = __expf(m_r[i] - mnew);
            m_r[i] = mnew;
            float rs = 0.f;
            #pragma unroll
            for (int j = 0; j < 4; j++) {
                float p = __expf(sc[j] - mnew);
                Psm[r * AP + tx + 16 * j] = p;
                rs += p;
            }
            #pragma unroll
            for (int off = 8; off >= 1; off >>= 1)
                rs += __shfl_xor_sync(0xffffffffu, rs, off);
            l_r[i] = l_r[i] * scale + rs;
            if (tx == 0) {
                scale_sm[r] = scale;
                lsum_sm[r]  = l_r[i];
            }
        }
        __syncthreads();

        const float sA = scale_sm[sm0 + g];
        const float sB = scale_sm[sm0 + g + 8];
        #pragma unroll
        for (int nt = 0; nt < 4; nt++) {
            o_acc[nt][0] *= sA; o_acc[nt][1] *= sA;
            o_acc[nt][2] *= sB; o_acc[nt][3] *= sB;
        }
        #pragma unroll
        for (int kk = 0; kk < 64; kk += 8) {
            uint32_t ah[4], al[4];
            msplit(Psm[(sm0 + g) * AP + kk + t],         ah[0], al[0]);
            msplit(Psm[(sm0 + g + 8) * AP + kk + t],     ah[1], al[1]);
            msplit(Psm[(sm0 + g) * AP + kk + t + 4],     ah[2], al[2]);
            msplit(Psm[(sm0 + g + 8) * AP + kk + t + 4], ah[3], al[3]);
            #pragma unroll
            for (int nt = 0; nt < 4; nt++) {
                int n0 = pn0 + nt * 8;
                uint32_t bh0, bl0, bh1, bl1;
                msplit(Vs[(kk + t) * VP + n0 + g],     bh0, bl0);
                msplit(Vs[(kk + t + 4) * VP + n0 + g], bh1, bl1);
                mma_x3(o_acc[nt], ah, al, bh0, bh1, bl0, bl1);
            }
        }
    }

    __syncthreads();
    const float invA = 1.f / lsum_sm[sm0 + g];
    const float invB = 1.f / lsum_sm[sm0 + g + 8];
    const size_t row0 = (size_t)(b * TLEN + I0 + sm0 + g) * EDIM;
    const size_t row1 = row0 + 8 * EDIM;
    #pragma unroll
    for (int nt = 0; nt < 4; nt++) {
        size_t col = headOff + pn0 + nt * 8 + 2 * t;   // even
        uint32_t hA, lA, hB, lB;
        bsplit2(o_acc[nt][0] * invA, o_acc[nt][1] * invA, hA, lA);
        bsplit2(o_acc[nt][2] * invB, o_acc[nt][3] * invB, hB, lB);
        Oh[(row0 + col) >> 1] = hA;
        Ol[(row0 + col) >> 1] = lA;
        Oh[(row1 + col) >> 1] = hB;
        Ol[(row1 + col) >> 1] = lB;
    }
}

// ---------------------------------------------------------------------------
// Launch (7 launches total)
// ---------------------------------------------------------------------------
extern "C" void kernel_launch(void* const* d_in, const int* in_sizes, int n_in,
                              void* d_out, int out_size)
{
    const float* x     = (const float*)d_in[0];
    const float* Wq    = (const float*)d_in[1];
    const float* Wk    = (const float*)d_in[2];
    const float* Wkp   = (const float*)d_in[3];
    const float* Wv    = (const float*)d_in[4];
    const float* Wu    = (const float*)d_in[5];
    const float* bu    = (const float*)d_in[6];
    const float* parma = (const float*)d_in[7];
    const float* parmb = (const float*)d_in[8];
    const float* pos   = (const float*)d_in[9];
    float* out = (float*)d_out;

    float *Qb, *Kb, *Vb, *KPb, *dptb, *cppb;
    void *Xh, *Xl, *Ph, *Pl, *Wh, *Wl, *ATTh, *ATTl;
    cudaGetSymbolAddress((void**)&Qb,   g_Q);
    cudaGetSymbolAddress((void**)&Kb,   g_K);
    cudaGetSymbolAddress((void**)&Vb,   g_V);
    cudaGetSymbolAddress((void**)&KPb,  g_KP);
    cudaGetSymbolAddress((void**)&dptb, g_dpt);
    cudaGetSymbolAddress((void**)&cppb, g_cpp);
    cudaGetSymbolAddress(&Xh,  g_Xh);
    cudaGetSymbolAddress(&Xl,  g_Xl);
    cudaGetSymbolAddress(&Ph,  g_Ph);
    cudaGetSymbolAddress(&Pl,  g_Pl);
    cudaGetSymbolAddress(&Wh,  g_Wh);
    cudaGetSymbolAddress(&Wl,  g_Wl);
    cudaGetSymbolAddress(&ATTh, g_ATTh);
    cudaGetSymbolAddress(&ATTl, g_ATTl);

    // 1) transpose + split weights into bf16 planes
    transpose5_kernel<<<dim3(32, 32, 5), dim3(32, 8)>>>(
        Wq, Wk, Wv, Wkp, Wu, (__nv_bfloat16*)Wh, (__nv_bfloat16*)Wl);

    // 2) split x and pos into planes
    const int xpairs = BATCH * TLEN * EDIM / 2;          // 2,097,152
    const int ppairs = P2 * EDIM / 2;                    // 1,048,064
    cvt_planes_kernel<<<(xpairs + 255) / 256, 256>>>(
        (const float2*)x, (uint32_t*)Xh, (uint32_t*)Xl, xpairs);
    cvt_planes_kernel<<<(ppairs + 255) / 256, 256>>>(
        (const float2*)pos, (uint32_t*)Ph, (uint32_t*)Pl, ppairs);

    // 3) fused Q/K/V/KP projections (bf16x3)
    cudaFuncSetAttribute(fused_gemm_kernel,
                         cudaFuncAttributeMaxDynamicSharedMemorySize,
                         GEMM_SMEM_BYTES);
    fused_gemm_kernel<<<dim3(8, 32, 4), 256, GEMM_SMEM_BYTES>>>(
        (const uint32_t*)Xh, (const uint32_t*)Xl,
        (const uint32_t*)Ph, (const uint32_t*)Pl,
        (const uint32_t*)Wh, (const uint32_t*)Wl, Qb, Kb, Vb, KPb);

    // 4) fused dpt + cpp
    const int total_small = BATCH * HEADS * TLEN + HEADS * P2;
    dptcpp_kernel<<<(total_small + 255) / 256, 256>>>(Kb, KPb, parma, parmb,
                                                      dptb, cppb);

    // 5) attention (writes ATT bf16 planes)
    size_t smemBytes = (size_t)ATTN_SMEM_FLOATS * sizeof(float);
    cudaFuncSetAttribute(attn_kernel,
                         cudaFuncAttributeMaxDynamicSharedMemorySize,
                         (int)smemBytes);
    attn_kernel<<<dim3(TLEN / 64, HEADS, BATCH), 256, smemBytes>>>(
        Qb, Kb, Vb, KPb, dptb, cppb, (uint32_t*)ATTh, (uint32_t*)ATTl);

    // 6) output projection (+bias, bf16x3)
    cudaFuncSetAttribute(gemmU_kernel,
                         cudaFuncAttributeMaxDynamicSharedMemorySize,
                         GEMM_SMEM_BYTES);
    gemmU_kernel<<<dim3(8, 32), 256, GEMM_SMEM_BYTES>>>(
        (const uint32_t*)ATTh, (const uint32_t*)ATTl,
        (const uint32_t*)Wh + 4 * (size_t)EDIM * EDIM / 2,
        (const uint32_t*)Wl + 4 * (size_t)EDIM * EDIM / 2,
        bu, out);
}

// round 12
// speedup vs baseline: 1.4104x; 1.1618x over previous
#include <cuda_runtime.h>
#include <cuda_bf16.h>
#include <math.h>
#include <stdint.h>

// Problem constants
#define BATCH 4
#define TLEN  1024
#define EDIM  1024
#define HEADS 16
#define SDIM  64
#define P2    2047   // 2*t - 1

// ---------------------------------------------------------------------------
// Scratch (device globals — no runtime allocation allowed)
// ---------------------------------------------------------------------------
__device__ float g_V  [(size_t)BATCH * TLEN * EDIM];
__device__ float g_dpt[(size_t)BATCH * HEADS * TLEN];
__device__ float g_cpp[(size_t)HEADS * P2];
// bf16 hi/lo planes
__device__ __nv_bfloat16 g_Xh [(size_t)BATCH * TLEN * EDIM];
__device__ __nv_bfloat16 g_Xl [(size_t)BATCH * TLEN * EDIM];
__device__ __nv_bfloat16 g_Psrch[(size_t)P2 * EDIM];
__device__ __nv_bfloat16 g_Psrcl[(size_t)P2 * EDIM];
__device__ __nv_bfloat16 g_Wh [(size_t)5 * EDIM * EDIM];  // transposed [N,K]
__device__ __nv_bfloat16 g_Wl [(size_t)5 * EDIM * EDIM];
__device__ __nv_bfloat16 g_Qh [(size_t)BATCH * TLEN * EDIM];
__device__ __nv_bfloat16 g_Ql [(size_t)BATCH * TLEN * EDIM];
__device__ __nv_bfloat16 g_Kh [(size_t)BATCH * TLEN * EDIM];
__device__ __nv_bfloat16 g_Kl [(size_t)BATCH * TLEN * EDIM];
__device__ __nv_bfloat16 g_KPh[(size_t)P2 * EDIM];
__device__ __nv_bfloat16 g_KPl[(size_t)P2 * EDIM];
__device__ __nv_bfloat16 g_ATTh[(size_t)BATCH * TLEN * EDIM];
__device__ __nv_bfloat16 g_ATTl[(size_t)BATCH * TLEN * EDIM];

// ---------------------------------------------------------------------------
// helpers
// ---------------------------------------------------------------------------
__device__ __forceinline__ void msplit(float x, uint32_t& hi, uint32_t& lo) {
    uint32_t h = __float_as_uint(x) & 0xFFFFE000u;   // tf32 mask split
    hi = h;
    lo = __float_as_uint(x - __uint_as_float(h));
}
__device__ __forceinline__ void mma_tf32(float* c,
    uint32_t a0, uint32_t a1, uint32_t a2, uint32_t a3,
    uint32_t b0, uint32_t b1)
{
    asm volatile(
        "mma.sync.aligned.m16n8k8.row.col.f32.tf32.tf32.f32 "
        "{%0,%1,%2,%3}, {%4,%5,%6,%7}, {%8,%9}, {%0,%1,%2,%3};"
        : "+f"(c[0]), "+f"(c[1]), "+f"(c[2]), "+f"(c[3])
        : "r"(a0), "r"(a1), "r"(a2), "r"(a3), "r"(b0), "r"(b1));
}
__device__ __forceinline__ void mma_x3(float* c,
    const uint32_t* ah, const uint32_t* al,
    uint32_t bh0, uint32_t bh1, uint32_t bl0, uint32_t bl1)
{
    mma_tf32(c, al[0], al[1], al[2], al[3], bh0, bh1);
    mma_tf32(c, ah[0], ah[1], ah[2], ah[3], bl0, bl1);
    mma_tf32(c, ah[0], ah[1], ah[2], ah[3], bh0, bh1);
}
__device__ __forceinline__ void mma_bf16(float* c,
    uint32_t a0, uint32_t a1, uint32_t a2, uint32_t a3,
    uint32_t b0, uint32_t b1)
{
    asm volatile(
        "mma.sync.aligned.m16n8k16.row.col.f32.bf16.bf16.f32 "
        "{%0,%1,%2,%3}, {%4,%5,%6,%7}, {%8,%9}, {%0,%1,%2,%3};"
        : "+f"(c[0]), "+f"(c[1]), "+f"(c[2]), "+f"(c[3])
        : "r"(a0), "r"(a1), "r"(a2), "r"(a3), "r"(b0), "r"(b1));
}
__device__ __forceinline__ void mma_bf16_x3(float* c,
    const uint32_t* ah, const uint32_t* al,
    uint32_t bh0, uint32_t bh1, uint32_t bl0, uint32_t bl1)
{
    mma_bf16(c, al[0], al[1], al[2], al[3], bh0, bh1);
    mma_bf16(c, ah[0], ah[1], ah[2], ah[3], bl0, bl1);
    mma_bf16(c, ah[0], ah[1], ah[2], ah[3], bh0, bh1);
}
// pack two fp32 into (hi bf16x2, lo bf16x2)
__device__ __forceinline__ void bsplit2(float v0, float v1,
                                        uint32_t& hi, uint32_t& lo)
{
    __nv_bfloat162 h = __float22bfloat162_rn(make_float2(v0, v1));
    float r0 = v0 - __bfloat162float(h.x);
    float r1 = v1 - __bfloat162float(h.y);
    __nv_bfloat162 l = __float22bfloat162_rn(make_float2(r0, r1));
    hi = *(uint32_t*)&h;
    lo = *(uint32_t*)&l;
}
// reconstruct 2 fp32 from hi/lo words
__device__ __forceinline__ float2 brecon2(uint32_t h, uint32_t l) {
    __nv_bfloat162 hb = *(__nv_bfloat162*)&h;
    __nv_bfloat162 lb = *(__nv_bfloat162*)&l;
    return make_float2(__bfloat162float(hb.x) + __bfloat162float(lb.x),
                       __bfloat162float(hb.y) + __bfloat162float(lb.y));
}

// cp.async helpers (baseline PTX, sm_80+); v=false -> zero-fill 16B
__device__ __forceinline__ void cpa16(void* smem_dst, const void* gsrc, bool v) {
    uint32_t s = (uint32_t)__cvta_generic_to_shared(smem_dst);
    int sz = v ? 16 : 0;
    asm volatile("cp.async.cg.shared.global [%0], [%1], 16, %2;"
                 :: "r"(s), "l"(gsrc), "r"(sz) : "memory");
}
#define CP_COMMIT() asm volatile("cp.async.commit_group;" ::: "memory")
#define CP_WAIT1()  asm volatile("cp.async.wait_group 1;" ::: "memory")
#define CP_WAIT0()  asm volatile("cp.async.wait_group 0;" ::: "memory")

// ---------------------------------------------------------------------------
// Transpose 5 weights into bf16 hi/lo planes: dst[z][N][K] = split(src_z[K,N])
// ---------------------------------------------------------------------------
__global__ void __launch_bounds__(256) transpose5_kernel(
    const float* __restrict__ W0, const float* __restrict__ W1,
    const float* __restrict__ W2, const float* __restrict__ W3,
    const float* __restrict__ W4,
    __nv_bfloat16* __restrict__ dstHi, __nv_bfloat16* __restrict__ dstLo)
{
    __shared__ float t[32][33];
    int z = blockIdx.z;
    const float* src = (z == 0) ? W0 : (z == 1) ? W1 : (z == 2) ? W2
                     : (z == 3) ? W3 : W4;
    size_t base = (size_t)z * EDIM * EDIM;
    int bx = blockIdx.x * 32, by = blockIdx.y * 32;
    int x = threadIdx.x, y = threadIdx.y;   // block (32, 8)
    #pragma unroll
    for (int i = 0; i < 32; i += 8)
        t[y + i][x] = src[(size_t)(by + y + i) * EDIM + bx + x];
    __syncthreads();
    #pragma unroll
    for (int i = 0; i < 32; i += 8) {
        float v = t[x][y + i];
        __nv_bfloat16 hb = __float2bfloat16_rn(v);
        size_t o = base + (size_t)(bx + y + i) * EDIM + by + x;
        dstHi[o] = hb;
        dstLo[o] = __float2bfloat16_rn(v - __bfloat162float(hb));
    }
}

// ---------------------------------------------------------------------------
// Convert fp32 array to bf16 hi/lo planes (pairwise)
// ---------------------------------------------------------------------------
__global__ void __launch_bounds__(256) cvt_planes_kernel(
    const float2* __restrict__ src, uint32_t* __restrict__ hi,
    uint32_t* __restrict__ lo, int npairs)
{
    int i = blockIdx.x * 256 + threadIdx.x;
    if (i >= npairs) return;
    float2 v = src[i];
    uint32_t h, l;
    bsplit2(v.x, v.y, h, l);
    hi[i] = h;
    lo[i] = l;
}

// ---------------------------------------------------------------------------
// bf16x3 tensor-core GEMM tile. Output either fp32 (+bias) or bf16 planes.
// ---------------------------------------------------------------------------
#define GPW 20                         // uint32 words per smem plane row
#define PLANE_W (128 * GPW)            // 2560 words per plane
#define GEMM_SMEM_BYTES (8 * PLANE_W * 4)   // 81920 B

__device__ __forceinline__ void gemm_stage_bf16(
    uint32_t* s,
    const uint32_t* __restrict__ Ah, const uint32_t* __restrict__ Al,
    const uint32_t* __restrict__ Bh, const uint32_t* __restrict__ Bl,
    int M, int bm, int bn, int koffw, int tid)
{
    #pragma unroll
    for (int r = 0; r < 2; r++) {
        int slot = tid + 256 * r;          // 0..511
        int row = slot >> 2, ch = (slot & 3) * 4;
        int grow = bm + row;
        bool v = grow < M;
        size_t ga = (size_t)(v ? grow : 0) * 512 + koffw + ch;
        size_t gb = (size_t)(bn + row) * 512 + koffw + ch;
        uint32_t* sd = s + row * GPW + ch;
        cpa16(sd,               &Ah[ga], v);
        cpa16(sd + PLANE_W,     &Al[ga], v);
        cpa16(sd + 2 * PLANE_W, &Bh[gb], true);
        cpa16(sd + 3 * PLANE_W, &Bl[gb], true);
    }
    CP_COMMIT();
}

__device__ __forceinline__ void gemm_tile(
    const uint32_t* __restrict__ Ah, const uint32_t* __restrict__ Al,
    const uint32_t* __restrict__ Bh, const uint32_t* __restrict__ Bl,
    const float* __restrict__ bias, float* __restrict__ Cf,
    uint32_t* __restrict__ Ch, uint32_t* __restrict__ Cl,
    int M, int hasBias, int bm, int bn)
{
    extern __shared__ uint32_t gsm[];
    uint32_t* buf0 = gsm;
    uint32_t* buf1 = gsm + 4 * PLANE_W;

    const int tid  = threadIdx.x;
    const int wid  = tid >> 5;
    const int lane = tid & 31;
    const int wm = wid & 1;
    const int wn = wid >> 1;
    const int g = lane >> 2;
    const int t = lane & 3;

    gemm_stage_bf16(buf0, Ah, Al, Bh, Bl, M, bm, bn, 0,  tid);
    gemm_stage_bf16(buf1, Ah, Al, Bh, Bl, M, bm, bn, 16, tid);

    float acc[4][4][4];
    #pragma unroll
    for (int mi = 0; mi < 4; mi++)
        #pragma unroll
        for (int ni = 0; ni < 4; ni++)
            #pragma unroll
            for (int q = 0; q < 4; q++) acc[mi][ni][q] = 0.f;

    #pragma unroll 1
    for (int kt = 0; kt < 32; kt++) {
        if (kt + 1 < 32) CP_WAIT1(); else CP_WAIT0();
        __syncthreads();
        const uint32_t* s = (kt & 1) ? buf1 : buf0;
        const uint32_t* Ahs = s;
        const uint32_t* Als = s + PLANE_W;
        const uint32_t* Bhs = s + 2 * PLANE_W;
        const uint32_t* Bls = s + 3 * PLANE_W;

        #pragma unroll
        for (int ks = 0; ks < 2; ks++) {
            const int kb = ks * 8;
            uint32_t ah[4][4], al[4][4];
            #pragma unroll
            for (int mi = 0; mi < 4; mi++) {
                int r0 = wm * 64 + mi * 16 + g;
                ah[mi][0] = Ahs[r0 * GPW + kb + t];
                ah[mi][1] = Ahs[(r0 + 8) * GPW + kb + t];
                ah[mi][2] = Ahs[r0 * GPW + kb + t + 4];
                ah[mi][3] = Ahs[(r0 + 8) * GPW + kb + t + 4];
                al[mi][0] = Als[r0 * GPW + kb + t];
                al[mi][1] = Als[(r0 + 8) * GPW + kb + t];
                al[mi][2] = Als[r0 * GPW + kb + t + 4];
                al[mi][3] = Als[(r0 + 8) * GPW + kb + t + 4];
            }
            #pragma unroll
            for (int ni = 0; ni < 4; ni++) {
                int rn = wn * 32 + ni * 8 + g;
                uint32_t bh0 = Bhs[rn * GPW + kb + t];
                uint32_t bh1 = Bhs[rn * GPW + kb + t + 4];
                uint32_t bl0 = Bls[rn * GPW + kb + t];
                uint32_t bl1 = Bls[rn * GPW + kb + t + 4];
                #pragma unroll
                for (int mi = 0; mi < 4; mi++)
                    mma_bf16_x3(acc[mi][ni], ah[mi], al[mi], bh0, bh1, bl0, bl1);
            }
        }
        __syncthreads();
        if (kt + 2 < 32)
            gemm_stage_bf16((kt & 1) ? buf1 : buf0, Ah, Al, Bh, Bl,
                            M, bm, bn, (kt + 2) * 16, tid);
    }

    #pragma unroll
    for (int mi = 0; mi < 4; mi++) {
        int row0 = bm + wm * 64 + mi * 16 + g;
        #pragma unroll
        for (int ni = 0; ni < 4; ni++) {
            int col = bn + wn * 32 + ni * 8 + t * 2;
            if (Cf) {
                float b0 = hasBias ? bias[col] : 0.f;
                float b1 = hasBias ? bias[col + 1] : 0.f;
                if (row0 < M) {
                    Cf[(size_t)row0 * EDIM + col]     = acc[mi][ni][0] + b0;
                    Cf[(size_t)row0 * EDIM + col + 1] = acc[mi][ni][1] + b1;
                }
                if (row0 + 8 < M) {
                    Cf[(size_t)(row0 + 8) * EDIM + col]     = acc[mi][ni][2] + b0;
                    Cf[(size_t)(row0 + 8) * EDIM + col + 1] = acc[mi][ni][3] + b1;
                }
            } else {
                uint32_t h, l;
                if (row0 < M) {
                    bsplit2(acc[mi][ni][0], acc[mi][ni][1], h, l);
                    size_t w = (size_t)row0 * 512 + (col >> 1);
                    Ch[w] = h; Cl[w] = l;
                }
                if (row0 + 8 < M) {
                    bsplit2(acc[mi][ni][2], acc[mi][ni][3], h, l);
                    size_t w = (size_t)(row0 + 8) * 512 + (col >> 1);
                    Ch[w] = h; Cl[w] = l;
                }
            }
        }
    }
}

// Fused projections: z=0 Q planes, z=1 K planes, z=2 V fp32, z=3 KP planes.
__global__ void __launch_bounds__(256, 2) fused_gemm_kernel(
    const uint32_t* __restrict__ Xh, const uint32_t* __restrict__ Xl,
    const uint32_t* __restrict__ Ph, const uint32_t* __restrict__ Pl,
    const uint32_t* __restrict__ Wh, const uint32_t* __restrict__ Wl,
    uint32_t* __restrict__ Qh, uint32_t* __restrict__ Ql,
    uint32_t* __restrict__ Kh, uint32_t* __restrict__ Kl,
    float* __restrict__ Vb,
    uint32_t* __restrict__ KPh, uint32_t* __restrict__ KPl)
{
    const int z = blockIdx.z;
    const uint32_t* Ah = (z < 3) ? Xh : Ph;
    const uint32_t* Al = (z < 3) ? Xl : Pl;
    const int M = (z < 3) ? (BATCH * TLEN) : P2;
    const int bm = blockIdx.y * 128;
    if (bm >= M) return;
    const uint32_t* Bh = Wh + (size_t)z * EDIM * EDIM / 2;
    const uint32_t* Bl = Wl + (size_t)z * EDIM * EDIM / 2;
    float* Cf = (z == 2) ? Vb : nullptr;
    uint32_t* Ch = (z == 0) ? Qh : (z == 1) ? Kh : (z == 3) ? KPh : nullptr;
    uint32_t* Cl = (z == 0) ? Ql : (z == 1) ? Kl : (z == 3) ? KPl : nullptr;
    gemm_tile(Ah, Al, Bh, Bl, nullptr, Cf, Ch, Cl, M, 0, bm, blockIdx.x * 128);
}

__global__ void __launch_bounds__(256, 2) gemmU_kernel(
    const uint32_t* __restrict__ Ah, const uint32_t* __restrict__ Al,
    const uint32_t* __restrict__ Bh, const uint32_t* __restrict__ Bl,
    const float* __restrict__ bias, float* __restrict__ C)
{
    gemm_tile(Ah, Al, Bh, Bl, bias, C, nullptr, nullptr, BATCH * TLEN, 1,
              blockIdx.y * 128, blockIdx.x * 128);
}

// ---------------------------------------------------------------------------
// Fused dpt + cpp (reads bf16 planes, reconstructs hi+lo)
// ---------------------------------------------------------------------------
__global__ void __launch_bounds__(256) dptcpp_kernel(
    const uint32_t* __restrict__ Kh, const uint32_t* __restrict__ Kl,
    const uint32_t* __restrict__ KPh, const uint32_t* __restrict__ KPl,
    const float* __restrict__ parma, const float* __restrict__ parmb,
    float* __restrict__ dpt, float* __restrict__ cpp)
{
    int idx = blockIdx.x * 256 + threadIdx.x;
    if (idx < BATCH * HEADS * TLEN) {
        int j = idx & (TLEN - 1);
        int h = (idx >> 10) & (HEADS - 1);
        int b = idx >> 14;
        size_t base = (size_t)(b * TLEN + j) * 512 + h * 32;
        const float* pa = parma + h * SDIM;
        float s = 0.f;
        #pragma unroll
        for (int w = 0; w < 32; w++) {
            float2 f = brecon2(Kh[base + w], Kl[base + w]);
            s = fmaf(pa[2 * w], f.x, s);
            s = fmaf(pa[2 * w + 1], f.y, s);
        }
        dpt[idx] = s;
    } else {
        int i2 = idx - BATCH * HEADS * TLEN;
        if (i2 >= HEADS * P2) return;
        int h = i2 / P2;
        int p = i2 - h * P2;
        size_t base = (size_t)p * 512 + h * 32;
        const float* pb = parmb + h * SDIM;
        float s = 0.f;
        #pragma unroll
        for (int w = 0; w < 32; w++) {
            float2 f = brecon2(KPh[base + w], KPl[base + w]);
            s = fmaf(pb[2 * w], f.x, s);
            s = fmaf(pb[2 * w + 1], f.y, s);
        }
        cpp[i2] = s;
    }
}

// ---------------------------------------------------------------------------
// Tensor-core attention: scores = bf16x3 (k16) on pre-split Q/K/KP planes;
// softmax fp32; PV = tf32x3 on fp32 P and V. Band-masked E fragments.
// One CTA per (b,h,64-row i-tile), 256 threads.
// ---------------------------------------------------------------------------
#define QW 36    // word stride for bf16 plane rows (banks 4g+t conflict-free)
#define VP 72    // V fp32 stride: banks 8t+g for PV reads
#define SP 196   // S matrix stride (floats)

// word layout offsets
#define OFF_QH 0
#define OFF_QL 2304
#define OFF_BH 4608
#define OFF_BL 11520
#define OFF_VS 18432
#define OFF_PS 23040
#define OFF_DP 27392
#define OFF_CP 27456
#define OFF_SC 27584
#define OFF_LS 27648
#define ATTN_SMEM_BYTES (27712 * 4)

__global__ void __launch_bounds__(256, 2) attn_kernel(
    const uint32_t* __restrict__ Qh, const uint32_t* __restrict__ Ql,
    const uint32_t* __restrict__ Kh, const uint32_t* __restrict__ Kl,
    const float* __restrict__ V,
    const uint32_t* __restrict__ KPh, const uint32_t* __restrict__ KPl,
    const float* __restrict__ dpt, const float* __restrict__ cpp,
    uint32_t* __restrict__ Oh, uint32_t* __restrict__ Ol)
{
    extern __shared__ uint32_t smw[];
    uint32_t* Qhs = smw + OFF_QH;       // [64][QW]
    uint32_t* Qls = smw + OFF_QL;
    uint32_t* Bhs = smw + OFF_BH;       // [192][QW] K rows 0..63, KP 64..191
    uint32_t* Bls = smw + OFF_BL;
    float* Ssm  = (float*)(smw + OFF_BH);   // [64][SP] aliases Bh/Bl block
    float* Vs   = (float*)(smw + OFF_VS);   // [64][VP]
    float* Psm  = (float*)(smw + OFF_PS);   // [64][68]
    float* dpts = (float*)(smw + OFF_DP);
    float* cpps = (float*)(smw + OFF_CP);
    float* scale_sm = (float*)(smw + OFF_SC);
    float* lsum_sm  = (float*)(smw + OFF_LS);

    const int tid  = threadIdx.x;
    const int lane = tid & 31;
    const int wid  = tid >> 5;
    const int g = lane >> 2;
    const int t = lane & 3;
    const int rm = (wid & 1) * 32;      // scores m-base
    const int cn = (wid >> 1) * 48;     // scores n-base
    const int sm0 = (wid & 3) * 16;     // PV m-slice
    const int pn0 = (wid >> 2) * 32;    // PV n-slice
    const int tx = tid & 15, ty = tid >> 4;

    const int b = blockIdx.z, h = blockIdx.y;
    const int it = (int)gridDim.x - 1 - (int)blockIdx.x;
    const int I0 = it * 64;
    const int hw = h * 32;              // head word offset in plane rows

    // Stage Q planes once (cp.async): 64 rows x 32 words per plane
    for (int idx = tid; idx < 512; idx += 256) {
        int r = idx >> 3, w = (idx & 7) * 4;
        size_t gq = (size_t)(b * TLEN + I0 + r) * 512 + hw + w;
        cpa16(&Qhs[r * QW + w], &Qh[gq], true);
        cpa16(&Qls[r * QW + w], &Ql[gq], true);
    }
    CP_COMMIT();

    float m_r[4], l_r[4];
    #pragma unroll
    for (int i = 0; i < 4; i++) { m_r[i] = -INFINITY; l_r[i] = 0.f; }
    float o_acc[4][4];
    #pragma unroll
    for (int n = 0; n < 4; n++)
        #pragma unroll
        for (int q = 0; q < 4; q++) o_acc[n][q] = 0.f;

    for (int jt = 0; jt <= it; jt++) {
        const int J0 = jt * 64;
        const int pbase = I0 + J0;
        const int d = I0 - J0;

        __syncthreads();

        // ---- Stage K planes, KP planes, V fp32 via cp.async ----
        for (int idx = tid; idx < 512; idx += 256) {
            int c = idx >> 3, w = (idx & 7) * 4;
            size_t gk = (size_t)(b * TLEN + J0 + c) * 512 + hw + w;
            cpa16(&Bhs[c * QW + w], &Kh[gk], true);
            cpa16(&Bls[c * QW + w], &Kl[gk], true);
        }
        for (int idx = tid; idx < 1024; idx += 256) {
            int pl = idx >> 3, w = (idx & 7) * 4;
            int p = pbase + pl;
            bool v = p < P2;
            size_t gp = (size_t)(v ? p : 0) * 512 + hw + w;
            cpa16(&Bhs[(64 + pl) * QW + w], &KPh[gp], v);
            cpa16(&Bls[(64 + pl) * QW + w], &KPl[gp], v);
        }
        for (int idx = tid; idx < 1024; idx += 256) {
            int j = idx >> 4, s4 = (idx & 15) << 2;
            cpa16(&Vs[j * VP + s4],
                  &V[((size_t)(b * TLEN + J0 + j)) * EDIM + h * SDIM + s4], true);
        }
        CP_COMMIT();
        if (tid < 64) dpts[tid] = dpt[((size_t)(b * HEADS + h)) * TLEN + J0 + tid];
        if (tid < 128) {
            int p = pbase + tid;
            cpps[tid] = (p < P2) ? cpp[(size_t)h * P2 + p] : 0.f;
        }
        CP_WAIT0();
        __syncthreads();

        // ---- Fragment need-masks (warp-uniform) ----
        bool need[2][6];
        #pragma unroll
        for (int mi = 0; mi < 2; mi++) {
            int m0 = rm + 16 * mi;
            int cmax = m0 + 15 + d; if (cmax > 63) cmax = 63;
            #pragma unroll
            for (int nt = 0; nt < 6; nt++) {
                int n0 = cn + nt * 8;
                if (n0 < 64) {
                    need[mi][nt] = (n0 <= m0 + 15 + d);
                } else {
                    int pl0 = n0 - 64;
                    need[mi][nt] = (pl0 + 7 >= m0) && (pl0 <= m0 + 15 + cmax);
                }
            }
        }

        // ---- Scores mma: bf16x3 m16n8k16, 4 k-chunks ----
        float sacc[2][6][4];
        #pragma unroll
        for (int mi = 0; mi < 2; mi++)
            #pragma unroll
            for (int n = 0; n < 6; n++)
                #pragma unroll
                for (int q = 0; q < 4; q++) sacc[mi][n][q] = 0.f;

        #pragma unroll
        for (int kc = 0; kc < 4; kc++) {
            const int kb = kc * 8;
            uint32_t ah[2][4], al[2][4];
            #pragma unroll
            for (int mi = 0; mi < 2; mi++) {
                int r0 = rm + 16 * mi + g;
                ah[mi][0] = Qhs[r0 * QW + kb + t];
                ah[mi][1] = Qhs[(r0 + 8) * QW + kb + t];
                ah[mi][2] = Qhs[r0 * QW + kb + t + 4];
                ah[mi][3] = Qhs[(r0 + 8) * QW + kb + t + 4];
                al[mi][0] = Qls[r0 * QW + kb + t];
                al[mi][1] = Qls[(r0 + 8) * QW + kb + t];
                al[mi][2] = Qls[r0 * QW + kb + t + 4];
                al[mi][3] = Qls[(r0 + 8) * QW + kb + t + 4];
            }
            #pragma unroll
            for (int nt = 0; nt < 6; nt++) {
                if (!need[0][nt] && !need[1][nt]) continue;
                int n0 = cn + nt * 8;
                uint32_t bh0 = Bhs[(n0 + g) * QW + kb + t];
                uint32_t bh1 = Bhs[(n0 + g) * QW + kb + t + 4];
                uint32_t bl0 = Bls[(n0 + g) * QW + kb + t];
                uint32_t bl1 = Bls[(n0 + g) * QW + kb + t + 4];
                if (need[0][nt])
                    mma_bf16_x3(sacc[0][nt], ah[0], al[0], bh0, bh1, bl0, bl1);
                if (need[1][nt])
                    mma_bf16_x3(sacc[1][nt], ah[1], al[1], bh0, bh1, bl0, bl1);
            }
        }

        __syncthreads();   // done reading B planes; overwrite as Ssm
        #pragma unroll
        for (int mi = 0; mi < 2; mi++) {
            int r0 = rm + 16 * mi + g;
            #pragma unroll
            for (int nt = 0; nt < 6; nt++) {
                if (!need[mi][nt]) continue;
                int n0 = cn + nt * 8 + 2 * t;
                Ssm[r0 * SP + n0]           = sacc[mi][nt][0];
                Ssm[r0 * SP + n0 + 1]       = sacc[mi][nt][1];
                Ssm[(r0 + 8) * SP + n0]     = sacc[mi][nt][2];
                Ssm[(r0 + 8) * SP + n0 + 1] = sacc[mi][nt][3];
            }
        }
        __syncthreads();

        // ---- Softmax (fp32 SIMT) ----
        #pragma unroll
        for (int i = 0; i < 4; i++) {
            int r = ty + 16 * i;
            float sc[4];
            float mx = -INFINITY;
            #pragma unroll
            for (int j = 0; j < 4; j++) {
                int c = tx + 16 * j;
                float v = Ssm[r * SP + c] + Ssm[r * SP + 64 + r + c]
                        + dpts[c] + cpps[r + c];
                if (c > r + d) v = -1e30f;
                sc[j] = v;
                mx = fmaxf(mx, v);
            }
            #pragma unroll
            for (int off = 8; off >= 1; off >>= 1)
                mx = fmaxf(mx, __shfl_xor_sync(0xffffffffu, mx, off));
            float mnew = fmaxf(m_r[i], mx);
            float scale = __expf(m_r[i] - mnew);
            m_r[i] = mnew;
            float rs = 0.f;
            #pragma unroll
            for (int j = 0; j < 4; j++) {
                float p = __expf(sc[j] - mnew);
                Psm[r * 68 + tx + 16 * j] = p;
                rs += p;
            }
            #pragma unroll
            for (int off = 8; off >= 1; off >>= 1)
                rs += __shfl_xor_sync(0xffffffffu, rs, off);
            l_r[i] = l_r[i] * scale + rs;
            if (tx == 0) {
                scale_sm[r] = scale;
                lsum_sm[r]  = l_r[i];
            }
        }
        __syncthreads();

        // ---- PV mma: O = O*scale + P @ V (tf32x3) ----
        const float sA = scale_sm[sm0 + g];
        const float sB = scale_sm[sm0 + g + 8];
        #pragma unroll
        for (int nt = 0; nt < 4; nt++) {
            o_acc[nt][0] *= sA; o_acc[nt][1] *= sA;
            o_acc[nt][2] *= sB; o_acc[nt][3] *= sB;
        }
        #pragma unroll
        for (int kk = 0; kk < 64; kk += 8) {
            uint32_t ah[4], al[4];
            msplit(Psm[(sm0 + g) * 68 + kk + t],         ah[0], al[0]);
            msplit(Psm[(sm0 + g + 8) * 68 + kk + t],     ah[1], al[1]);
            msplit(Psm[(sm0 + g) * 68 + kk + t + 4],     ah[2], al[2]);
            msplit(Psm[(sm0 + g + 8) * 68 + kk + t + 4], ah[3], al[3]);
            #pragma unroll
            for (int nt = 0; nt < 4; nt++) {
                int n0 = pn0 + nt * 8;
                uint32_t bh0, bl0, bh1, bl1;
                msplit(Vs[(kk + t) * VP + n0 + g],     bh0, bl0);
                msplit(Vs[(kk + t + 4) * VP + n0 + g], bh1, bl1);
                mma_x3(o_acc[nt], ah, al, bh0, bh1, bl0, bl1);
            }
        }
    }

    __syncthreads();
    const float invA = 1.f / lsum_sm[sm0 + g];
    const float invB = 1.f / lsum_sm[sm0 + g + 8];
    const size_t row0 = (size_t)(b * TLEN + I0 + sm0 + g) * EDIM;
    const size_t row1 = row0 + 8 * EDIM;
    #pragma unroll
    for (int nt = 0; nt < 4; nt++) {
        size_t col = (size_t)h * SDIM + pn0 + nt * 8 + 2 * t;   // even
        uint32_t hA, lA, hB, lB;
        bsplit2(o_acc[nt][0] * invA, o_acc[nt][1] * invA, hA, lA);
        bsplit2(o_acc[nt][2] * invB, o_acc[nt][3] * invB, hB, lB);
        Oh[(row0 + col) >> 1] = hA;
        Ol[(row0 + col) >> 1] = lA;
        Oh[(row1 + col) >> 1] = hB;
        Ol[(row1 + col) >> 1] = lB;
    }
}

// ---------------------------------------------------------------------------
// Launch
// ---------------------------------------------------------------------------
extern "C" void kernel_launch(void* const* d_in, const int* in_sizes, int n_in,
                              void* d_out, int out_size)
{
    const float* x     = (const float*)d_in[0];
    const float* Wq    = (const float*)d_in[1];
    const float* Wk    = (const float*)d_in[2];
    const float* Wkp   = (const float*)d_in[3];
    const float* Wv    = (const float*)d_in[4];
    const float* Wu    = (const float*)d_in[5];
    const float* bu    = (const float*)d_in[6];
    const float* parma = (const float*)d_in[7];
    const float* parmb = (const float*)d_in[8];
    const float* pos   = (const float*)d_in[9];
    float* out = (float*)d_out;

    float *Vb, *dptb, *cppb;
    void *Xh, *Xl, *Ph, *Pl, *Wh, *Wl, *Qh, *Ql, *Kh, *Kl, *KPh, *KPl, *ATTh, *ATTl;
    cudaGetSymbolAddress((void**)&Vb,   g_V);
    cudaGetSymbolAddress((void**)&dptb, g_dpt);
    cudaGetSymbolAddress((void**)&cppb, g_cpp);
    cudaGetSymbolAddress(&Xh,  g_Xh);
    cudaGetSymbolAddress(&Xl,  g_Xl);
    cudaGetSymbolAddress(&Ph,  g_Psrch);
    cudaGetSymbolAddress(&Pl,  g_Psrcl);
    cudaGetSymbolAddress(&Wh,  g_Wh);
    cudaGetSymbolAddress(&Wl,  g_Wl);
    cudaGetSymbolAddress(&Qh,  g_Qh);
    cudaGetSymbolAddress(&Ql,  g_Ql);
    cudaGetSymbolAddress(&Kh,  g_Kh);
    cudaGetSymbolAddress(&Kl,  g_Kl);
    cudaGetSymbolAddress(&KPh, g_KPh);
    cudaGetSymbolAddress(&KPl, g_KPl);
    cudaGetSymbolAddress(&ATTh, g_ATTh);
    cudaGetSymbolAddress(&ATTl, g_ATTl);

    // 1) transpose + split weights into bf16 planes
    transpose5_kernel<<<dim3(32, 32, 5), dim3(32, 8)>>>(
        Wq, Wk, Wv, Wkp, Wu, (__nv_bfloat16*)Wh, (__nv_bfloat16*)Wl);

    // 2) split x and pos into planes
    const int xpairs = BATCH * TLEN * EDIM / 2;
    const int ppairs = P2 * EDIM / 2;
    cvt_planes_kernel<<<(xpairs + 255) / 256, 256>>>(
        (const float2*)x, (uint32_t*)Xh, (uint32_t*)Xl, xpairs);
    cvt_planes_kernel<<<(ppairs + 255) / 256, 256>>>(
        (const float2*)pos, (uint32_t*)Ph, (uint32_t*)Pl, ppairs);

    // 3) fused projections: Q/K/KP -> bf16 planes, V -> fp32
    cudaFuncSetAttribute(fused_gemm_kernel,
                         cudaFuncAttributeMaxDynamicSharedMemorySize,
                         GEMM_SMEM_BYTES);
    fused_gemm_kernel<<<dim3(8, 32, 4), 256, GEMM_SMEM_BYTES>>>(
        (const uint32_t*)Xh, (const uint32_t*)Xl,
        (const uint32_t*)Ph, (const uint32_t*)Pl,
        (const uint32_t*)Wh, (const uint32_t*)Wl,
        (uint32_t*)Qh, (uint32_t*)Ql, (uint32_t*)Kh, (uint32_t*)Kl,
        Vb, (uint32_t*)KPh, (uint32_t*)KPl);

    // 4) fused dpt + cpp (from planes)
    const int total_small = BATCH * HEADS * TLEN + HEADS * P2;
    dptcpp_kernel<<<(total_small + 255) / 256, 256>>>(
        (const uint32_t*)Kh, (const uint32_t*)Kl,
        (const uint32_t*)KPh, (const uint32_t*)KPl,
        parma, parmb, dptb, cppb);

    // 5) attention (bf16x3 scores, tf32x3 PV; writes ATT planes)
    cudaFuncSetAttribute(attn_kernel,
                         cudaFuncAttributeMaxDynamicSharedMemorySize,
                         ATTN_SMEM_BYTES);
    attn_kernel<<<dim3(TLEN / 64, HEADS, BATCH), 256, ATTN_SMEM_BYTES>>>(
        (const uint32_t*)Qh, (const uint32_t*)Ql,
        (const uint32_t*)Kh, (const uint32_t*)Kl,
        Vb, (const uint32_t*)KPh, (const uint32_t*)KPl,
        dptb, cppb, (uint32_t*)ATTh, (uint32_t*)ATTl);

    // 6) output projection (+bias, bf16x3)
    cudaFuncSetAttribute(gemmU_kernel,
                         cudaFuncAttributeMaxDynamicSharedMemorySize,
                         GEMM_SMEM_BYTES);
    gemmU_kernel<<<dim3(8, 32), 256, GEMM_SMEM_BYTES>>>(
        (const uint32_t*)ATTh, (const uint32_t*)ATTl,
        (const uint32_t*)Wh + 4 * (size_t)EDIM * EDIM / 2,
        (const uint32_t*)Wl + 4 * (size_t)EDIM * EDIM / 2,
        bu, out);
}